// round 1
// baseline (speedup 1.0000x reference)
#include <cuda_runtime.h>

#define BATCH 8
#define NPTS  4096
#define KNN   16
#define GRIDW 96
#define CELLS (BATCH * GRIDW * GRIDW)
#define MAXP  64
#define HID   128
#define OUTC  64
#define WPB   8   // warps (points) per MLP block

// Scratch (static device allocations are allowed)
__device__ int   g_cnt[CELLS];
__device__ int   g_pts[CELLS * MAXP];
__device__ float g_emb[BATCH * NPTS * 2 * KNN];

__global__ void k_zero() {
    int i = blockIdx.x * blockDim.x + threadIdx.x;
    if (i < CELLS) g_cnt[i] = 0;
}

__global__ void k_build(const float* __restrict__ xytp) {
    int i = blockIdx.x * blockDim.x + threadIdx.x;
    if (i >= BATCH * NPTS) return;
    float x = xytp[i * 4 + 1];
    float y = xytp[i * 4 + 2];
    int cx = min(GRIDW - 1, max(0, (int)(x * (float)GRIDW)));
    int cy = min(GRIDW - 1, max(0, (int)(y * (float)GRIDW)));
    int b = i >> 12;
    int cell = b * GRIDW * GRIDW + cy * GRIDW + cx;
    int p = atomicAdd(&g_cnt[cell], 1);
    if (p < MAXP) g_pts[cell * MAXP + p] = i & (NPTS - 1);
}

// Per query point: gather candidates from 3x3 cells, keep smallest-16 indices
// with d2 < R2 (replicating the reference's exact d2 float arithmetic), write
// the 32-float delta embedding.
__global__ void k_query(const float* __restrict__ xytp) {
    int i = blockIdx.x * blockDim.x + threadIdx.x;
    if (i >= BATCH * NPTS) return;
    int b = i >> 12;
    int n = i & (NPTS - 1);
    const float* base = xytp + (size_t)b * NPTS * 4;
    float xq = base[n * 4 + 1];
    float yq = base[n * 4 + 2];
    // sq = (x*x) + (y*y), each op individually rounded (match jnp.sum(xy*xy,-1))
    float sqn = __fadd_rn(__fmul_rn(xq, xq), __fmul_rn(yq, yq));
    const float R2 = (float)((5.0 / 480.0) * (5.0 / 480.0));

    int cx = min(GRIDW - 1, max(0, (int)(xq * (float)GRIDW)));
    int cy = min(GRIDW - 1, max(0, (int)(yq * (float)GRIDW)));
    int y0 = max(cy - 1, 0), y1 = min(cy + 1, GRIDW - 1);
    int x0 = max(cx - 1, 0), x1 = min(cx + 1, GRIDW - 1);

    int best[KNN];
    int cnt = 0;

    for (int gy = y0; gy <= y1; gy++) {
        for (int gx = x0; gx <= x1; gx++) {
            int cell = b * GRIDW * GRIDW + gy * GRIDW + gx;
            int c = min(g_cnt[cell], MAXP);
            int pbase = cell * MAXP;
            for (int j = 0; j < c; j++) {
                int m = g_pts[pbase + j];
                float xm = base[m * 4 + 1];
                float ym = base[m * 4 + 2];
                float sqm = __fadd_rn(__fmul_rn(xm, xm), __fmul_rn(ym, ym));
                // einsum K=2 contraction: fma chain, x first then y
                float dot = __fmaf_rn(yq, ym, __fmul_rn(xq, xm));
                float d2  = __fsub_rn(__fadd_rn(sqn, sqm), __fmul_rn(2.0f, dot));
                if (d2 < R2) {
                    if (cnt < KNN) {
                        int t = cnt++;
                        while (t > 0 && best[t - 1] > m) { best[t] = best[t - 1]; t--; }
                        best[t] = m;
                    } else if (m < best[KNN - 1]) {
                        int t = KNN - 1;
                        while (t > 0 && best[t - 1] > m) { best[t] = best[t - 1]; t--; }
                        best[t] = m;
                    }
                }
            }
        }
    }

    float* e = g_emb + (size_t)i * (2 * KNN);
    #pragma unroll
    for (int k = 0; k < KNN; k++) {
        int m = (k < cnt) ? best[k] : n;   // self-fill -> delta == 0 exactly
        float dx = __fsub_rn(xq, base[m * 4 + 1]);
        float dy = __fsub_rn(yq, base[m * 4 + 2]);
        e[2 * k]     = dx;
        e[2 * k + 1] = dy;
    }
}

// Warp-per-point MLP: emb[32] @ W1[32,128] + b1 -> relu -> @ W2[128,64] + b2
extern __shared__ float smem[];
__global__ void k_mlp(const float* __restrict__ W1, const float* __restrict__ b1,
                      const float* __restrict__ W2, const float* __restrict__ b2,
                      float* __restrict__ out) {
    float* sW1 = smem;                    // 32*128
    float* sW2 = sW1 + 32 * HID;          // 128*64
    float* sb1 = sW2 + HID * OUTC;        // 128
    float* sb2 = sb1 + HID;               // 64
    float* sh  = sb2 + OUTC;              // WPB*128

    int tid = threadIdx.x;
    for (int j = tid; j < 32 * HID;   j += blockDim.x) sW1[j] = W1[j];
    for (int j = tid; j < HID * OUTC; j += blockDim.x) sW2[j] = W2[j];
    if (tid < HID)  sb1[tid] = b1[tid];
    if (tid < OUTC) sb2[tid] = b2[tid];
    __syncthreads();

    int warp = tid >> 5;
    int lane = tid & 31;
    float* hrow = sh + warp * HID;
    const int total = BATCH * NPTS;

    for (int p = blockIdx.x * WPB + warp; p < total; p += gridDim.x * WPB) {
        float ev = g_emb[(size_t)p * 32 + lane];

        // Layer 1: lane owns hidden cols 4*lane .. 4*lane+3
        float4 acc;
        acc.x = sb1[4 * lane + 0];
        acc.y = sb1[4 * lane + 1];
        acc.z = sb1[4 * lane + 2];
        acc.w = sb1[4 * lane + 3];
        #pragma unroll
        for (int e = 0; e < 32; e++) {
            float v = __shfl_sync(0xffffffffu, ev, e);
            float4 w = *(const float4*)&sW1[e * HID + 4 * lane];
            acc.x = fmaf(v, w.x, acc.x);
            acc.y = fmaf(v, w.y, acc.y);
            acc.z = fmaf(v, w.z, acc.z);
            acc.w = fmaf(v, w.w, acc.w);
        }
        acc.x = fmaxf(acc.x, 0.0f);
        acc.y = fmaxf(acc.y, 0.0f);
        acc.z = fmaxf(acc.z, 0.0f);
        acc.w = fmaxf(acc.w, 0.0f);

        hrow[4 * lane + 0] = acc.x;
        hrow[4 * lane + 1] = acc.y;
        hrow[4 * lane + 2] = acc.z;
        hrow[4 * lane + 3] = acc.w;
        __syncwarp();

        // Layer 2: lane owns output cols 2*lane, 2*lane+1
        float ox = sb2[2 * lane + 0];
        float oy = sb2[2 * lane + 1];
        #pragma unroll 16
        for (int h = 0; h < HID; h++) {
            float hv = hrow[h];
            float2 w = *(const float2*)&sW2[h * OUTC + 2 * lane];
            ox = fmaf(hv, w.x, ox);
            oy = fmaf(hv, w.y, oy);
        }
        out[(size_t)p * OUTC + 2 * lane + 0] = ox;
        out[(size_t)p * OUTC + 2 * lane + 1] = oy;
        __syncwarp();   // protect hrow before next iteration
    }
}

extern "C" void kernel_launch(void* const* d_in, const int* in_sizes, int n_in,
                              void* d_out, int out_size) {
    const float* xytp = (const float*)d_in[0];
    const float* W1   = (const float*)d_in[1];
    const float* b1   = (const float*)d_in[2];
    const float* W2   = (const float*)d_in[3];
    const float* b2   = (const float*)d_in[4];
    float* out = (float*)d_out;

    k_zero<<<(CELLS + 255) / 256, 256>>>();
    k_build<<<(BATCH * NPTS + 255) / 256, 256>>>(xytp);
    k_query<<<(BATCH * NPTS + 127) / 128, 128>>>(xytp);

    const int smem_bytes = (32 * HID + HID * OUTC + HID + OUTC + WPB * HID) * (int)sizeof(float);
    cudaFuncSetAttribute(k_mlp, cudaFuncAttributeMaxDynamicSharedMemorySize, smem_bytes);
    k_mlp<<<592, WPB * 32, smem_bytes>>>(W1, b1, W2, b2, out);
}

// round 2
// speedup vs baseline: 1.6028x; 1.6028x over previous
#include <cuda_runtime.h>

#define BATCH 8
#define NPTS  4096
#define KNN   16
#define GRIDW 96
#define CELLS (BATCH * GRIDW * GRIDW)
#define MAXP  32
#define HID   128
#define OUTC  64
#define WPB   8   // warps per MLP block
#define PP    4   // points per warp

// Scratch (static device allocations are allowed)
__device__ int    g_cnt[CELLS];
__device__ float4 g_cell[CELLS * MAXP];              // (x, y, idx_as_float, unused)
__device__ float  g_emb[BATCH * NPTS * 2 * KNN];

__global__ void k_zero() {
    int i = blockIdx.x * blockDim.x + threadIdx.x;
    if (i < CELLS) g_cnt[i] = 0;
}

__global__ void k_build(const float4* __restrict__ xytp4) {
    int i = blockIdx.x * blockDim.x + threadIdx.x;
    if (i >= BATCH * NPTS) return;
    float4 v = xytp4[i];
    float x = v.y, y = v.z;
    int cx = min(GRIDW - 1, max(0, (int)(x * (float)GRIDW)));
    int cy = min(GRIDW - 1, max(0, (int)(y * (float)GRIDW)));
    int b = i >> 12;
    int cell = b * GRIDW * GRIDW + cy * GRIDW + cx;
    int p = atomicAdd(&g_cnt[cell], 1);
    if (p < MAXP) g_cell[cell * MAXP + p] = make_float4(x, y, __int_as_float(i & (NPTS - 1)), 0.f);
}

// Per query point: gather candidates from 3x3 cells, keep smallest-16 indices
// with d2 < R2, replicating the reference's exact float arithmetic.
__global__ void k_query(const float4* __restrict__ xytp4) {
    int i = blockIdx.x * blockDim.x + threadIdx.x;
    if (i >= BATCH * NPTS) return;
    int b = i >> 12;
    int n = i & (NPTS - 1);
    const float4* base4 = xytp4 + (size_t)b * NPTS;
    float4 q = base4[n];
    float xq = q.y, yq = q.z;
    float sqn = __fadd_rn(__fmul_rn(xq, xq), __fmul_rn(yq, yq));
    const float R2 = (float)((5.0 / 480.0) * (5.0 / 480.0));

    int cx = min(GRIDW - 1, max(0, (int)(xq * (float)GRIDW)));
    int cy = min(GRIDW - 1, max(0, (int)(yq * (float)GRIDW)));
    int y0 = max(cy - 1, 0), y1 = min(cy + 1, GRIDW - 1);
    int x0 = max(cx - 1, 0), x1 = min(cx + 1, GRIDW - 1);

    int best[KNN];
    int cnt = 0;

    for (int gy = y0; gy <= y1; gy++) {
        for (int gx = x0; gx <= x1; gx++) {
            int cell = b * GRIDW * GRIDW + gy * GRIDW + gx;
            int c = min(g_cnt[cell], MAXP);
            const float4* cp = g_cell + cell * MAXP;
            for (int j = 0; j < c; j++) {
                float4 pc = cp[j];
                float xm = pc.x, ym = pc.y;
                int   m  = __float_as_int(pc.z);
                float sqm = __fadd_rn(__fmul_rn(xm, xm), __fmul_rn(ym, ym));
                float dot = __fmaf_rn(yq, ym, __fmul_rn(xq, xm));
                float d2  = __fsub_rn(__fadd_rn(sqn, sqm), __fmul_rn(2.0f, dot));
                if (d2 < R2) {
                    if (cnt < KNN) {
                        int t = cnt++;
                        while (t > 0 && best[t - 1] > m) { best[t] = best[t - 1]; t--; }
                        best[t] = m;
                    } else if (m < best[KNN - 1]) {
                        int t = KNN - 1;
                        while (t > 0 && best[t - 1] > m) { best[t] = best[t - 1]; t--; }
                        best[t] = m;
                    }
                }
            }
        }
    }

    float* e = g_emb + (size_t)i * (2 * KNN);
    #pragma unroll
    for (int k = 0; k < KNN; k++) {
        if (k < cnt) {
            float4 t = base4[best[k]];
            e[2 * k]     = __fsub_rn(xq, t.y);
            e[2 * k + 1] = __fsub_rn(yq, t.z);
        } else {
            e[2 * k]     = 0.0f;   // self-gather -> exact zero delta
            e[2 * k + 1] = 0.0f;
        }
    }
}

// Warp processes PP=4 points: emb[32] @ W1[32,128] + b1 -> relu -> @ W2[128,64] + b2
extern __shared__ float smem[];
__global__ void __launch_bounds__(WPB * 32) k_mlp(
        const float* __restrict__ W1, const float* __restrict__ b1,
        const float* __restrict__ W2, const float* __restrict__ b2,
        float* __restrict__ out) {
    float* sW1 = smem;                    // 32*128
    float* sW2 = sW1 + 32 * HID;          // 128*64
    float* sb1 = sW2 + HID * OUTC;        // 128
    float* sb2 = sb1 + HID;               // 64
    float* sh  = sb2 + OUTC;              // WPB*PP*128

    int tid = threadIdx.x;
    for (int j = tid; j < 32 * HID;   j += blockDim.x) sW1[j] = W1[j];
    for (int j = tid; j < HID * OUTC; j += blockDim.x) sW2[j] = W2[j];
    if (tid < HID)  sb1[tid] = b1[tid];
    if (tid < OUTC) sb2[tid] = b2[tid];
    __syncthreads();

    int warp = tid >> 5;
    int lane = tid & 31;
    float* hr = sh + warp * (PP * HID);
    int p0 = (blockIdx.x * WPB + warp) * PP;   // grid sized so p0+PP <= total exactly

    // Load embeddings: lane holds emb column `lane` for PP points
    float ev[PP];
    #pragma unroll
    for (int pp = 0; pp < PP; pp++) ev[pp] = g_emb[(size_t)(p0 + pp) * 32 + lane];

    // Layer 1: lane owns hidden cols 4*lane..4*lane+3 for all PP points
    float4 acc[PP];
    float4 bb = *(const float4*)&sb1[4 * lane];
    #pragma unroll
    for (int pp = 0; pp < PP; pp++) acc[pp] = bb;

    #pragma unroll
    for (int e = 0; e < 32; e++) {
        float4 w = *(const float4*)&sW1[e * HID + 4 * lane];
        #pragma unroll
        for (int pp = 0; pp < PP; pp++) {
            float v = __shfl_sync(0xffffffffu, ev[pp], e);
            acc[pp].x = fmaf(v, w.x, acc[pp].x);
            acc[pp].y = fmaf(v, w.y, acc[pp].y);
            acc[pp].z = fmaf(v, w.z, acc[pp].z);
            acc[pp].w = fmaf(v, w.w, acc[pp].w);
        }
    }
    #pragma unroll
    for (int pp = 0; pp < PP; pp++) {
        acc[pp].x = fmaxf(acc[pp].x, 0.0f);
        acc[pp].y = fmaxf(acc[pp].y, 0.0f);
        acc[pp].z = fmaxf(acc[pp].z, 0.0f);
        acc[pp].w = fmaxf(acc[pp].w, 0.0f);
        *(float4*)&hr[pp * HID + 4 * lane] = acc[pp];
    }
    __syncwarp();

    // Layer 2: lane owns output cols 2*lane, 2*lane+1
    float2 o[PP];
    float2 b2v = *(const float2*)&sb2[2 * lane];
    #pragma unroll
    for (int pp = 0; pp < PP; pp++) o[pp] = b2v;

    #pragma unroll 8
    for (int h4 = 0; h4 < HID / 4; h4++) {
        float2 w0 = *(const float2*)&sW2[(4 * h4 + 0) * OUTC + 2 * lane];
        float2 w1 = *(const float2*)&sW2[(4 * h4 + 1) * OUTC + 2 * lane];
        float2 w2 = *(const float2*)&sW2[(4 * h4 + 2) * OUTC + 2 * lane];
        float2 w3 = *(const float2*)&sW2[(4 * h4 + 3) * OUTC + 2 * lane];
        #pragma unroll
        for (int pp = 0; pp < PP; pp++) {
            float4 hv = *(const float4*)&hr[pp * HID + 4 * h4];   // broadcast
            o[pp].x = fmaf(hv.x, w0.x, o[pp].x);
            o[pp].y = fmaf(hv.x, w0.y, o[pp].y);
            o[pp].x = fmaf(hv.y, w1.x, o[pp].x);
            o[pp].y = fmaf(hv.y, w1.y, o[pp].y);
            o[pp].x = fmaf(hv.z, w2.x, o[pp].x);
            o[pp].y = fmaf(hv.z, w2.y, o[pp].y);
            o[pp].x = fmaf(hv.w, w3.x, o[pp].x);
            o[pp].y = fmaf(hv.w, w3.y, o[pp].y);
        }
    }
    #pragma unroll
    for (int pp = 0; pp < PP; pp++)
        *(float2*)&out[(size_t)(p0 + pp) * OUTC + 2 * lane] = o[pp];
}

extern "C" void kernel_launch(void* const* d_in, const int* in_sizes, int n_in,
                              void* d_out, int out_size) {
    const float4* xytp4 = (const float4*)d_in[0];
    const float* W1 = (const float*)d_in[1];
    const float* b1 = (const float*)d_in[2];
    const float* W2 = (const float*)d_in[3];
    const float* b2 = (const float*)d_in[4];
    float* out = (float*)d_out;

    k_zero<<<(CELLS + 255) / 256, 256>>>();
    k_build<<<(BATCH * NPTS + 255) / 256, 256>>>(xytp4);
    k_query<<<(BATCH * NPTS + 127) / 128, 128>>>(xytp4);

    const int smem_bytes = (32 * HID + HID * OUTC + HID + OUTC + WPB * PP * HID) * (int)sizeof(float);
    cudaFuncSetAttribute(k_mlp, cudaFuncAttributeMaxDynamicSharedMemorySize, smem_bytes);
    int nblocks = (BATCH * NPTS) / (WPB * PP);   // 1024
    k_mlp<<<nblocks, WPB * 32, smem_bytes>>>(W1, b1, W2, b2, out);
}